// round 1
// baseline (speedup 1.0000x reference)
#include <cuda_runtime.h>
#include <cstdint>

// EdgeConv: B=16, N=8192, K=20, D=64
// Restructured: y[p][o] = x[p]·W[o,0:64]; z[p][o] = x[p]·(W[o,64:128]-W[o,0:64])
// out = gelu(LN(z + max_k y[ind]))

#define B_  16
#define N_  8192
#define K_  20
#define P_  (B_ * N_)   // 131072 points

// Scratch: per point, 128 floats: [0:64) = y, [64:128) = z.  67 MB.
__device__ float g_yz[(size_t)P_ * 128];

#define FMA2(d, a, b, c) \
    asm("fma.rn.f32x2 %0, %1, %2, %3;" : "=l"(d) : "l"(a), "l"(b), "l"(c))

// ---------------------------------------------------------------------------
// Kernel 1: yz[p][0:128] = x[p] (1x64) @ Wc (64x128)
// Wc[d][o] = W[o][d] (o<64) ; W[o-64][64+d] - W[o-64][d] (o>=64)
// Block: 256 thr, 128 points. Thread: 2 points x 32 outputs, f32x2 packed FMA.
// ---------------------------------------------------------------------------
__global__ __launch_bounds__(256, 2)
void k1_gemm(const float* __restrict__ x, const float* __restrict__ W)
{
    __shared__ float Wsm[64][128];
    for (int i = threadIdx.x; i < 64 * 128; i += 256) {
        int d = i >> 7, o = i & 127;
        float v;
        if (o < 64) v = W[o * 128 + d];
        else        v = W[(o - 64) * 128 + 64 + d] - W[(o - 64) * 128 + d];
        Wsm[d][o] = v;
    }
    __syncthreads();

    int pair  = threadIdx.x >> 2;          // 0..63
    int obase = (threadIdx.x & 3) * 32;    // 0,32,64,96
    size_t p0 = (size_t)blockIdx.x * 128 + (size_t)pair * 2;

    const float4* x0 = (const float4*)(x + p0 * 64);
    const float4* x1 = (const float4*)(x + (p0 + 1) * 64);

    unsigned long long a0[16], a1[16];
#pragma unroll
    for (int q = 0; q < 16; q++) { a0[q] = 0ull; a1[q] = 0ull; }

#pragma unroll 4
    for (int d4 = 0; d4 < 16; d4++) {
        float4 xa = __ldg(x0 + d4);
        float4 xb = __ldg(x1 + d4);
#pragma unroll
        for (int dd = 0; dd < 4; dd++) {
            float fa = (&xa.x)[dd];
            float fb = (&xb.x)[dd];
            unsigned long long pa, pb;
            asm("mov.b64 %0, {%1, %1};" : "=l"(pa) : "r"(__float_as_uint(fa)));
            asm("mov.b64 %0, {%1, %1};" : "=l"(pb) : "r"(__float_as_uint(fb)));
            const ulonglong2* wrow =
                (const ulonglong2*)&Wsm[d4 * 4 + dd][obase];  // 8 x (2 f32x2)
#pragma unroll
            for (int q = 0; q < 8; q++) {
                ulonglong2 w = wrow[q];
                FMA2(a0[2 * q],     pa, w.x, a0[2 * q]);
                FMA2(a0[2 * q + 1], pa, w.y, a0[2 * q + 1]);
                FMA2(a1[2 * q],     pb, w.x, a1[2 * q]);
                FMA2(a1[2 * q + 1], pb, w.y, a1[2 * q + 1]);
            }
        }
    }

    float* o0 = g_yz + p0 * 128 + obase;
    float* o1 = o0 + 128;
#pragma unroll
    for (int q = 0; q < 8; q++) {
        ((ulonglong2*)o0)[q] = make_ulonglong2(a0[2 * q], a0[2 * q + 1]);
        ((ulonglong2*)o1)[q] = make_ulonglong2(a1[2 * q], a1[2 * q + 1]);
    }
}

// ---------------------------------------------------------------------------
// Kernel 2: out[p][o] = gelu(LN(z[p][o] + max_k y[ind[p][k]][o]))
// Warp per point, lane holds dims (2*lane, 2*lane+1). 20 unrolled gathers.
// ---------------------------------------------------------------------------
__global__ __launch_bounds__(256)
void k2_gather(const int*   __restrict__ ind,
               const float* __restrict__ gamma,
               const float* __restrict__ beta,
               float*       __restrict__ out)
{
    int warp = threadIdx.x >> 5, lane = threadIdx.x & 31;
    size_t p = (size_t)blockIdx.x * 8 + warp;
    size_t bbase = (p >> 13) << 13;   // b * N

    int jv = 0;
    if (lane < K_) jv = ind[p * K_ + lane];

    float m0 = -3.402823466e+38f, m1 = -3.402823466e+38f;
#pragma unroll
    for (int k = 0; k < K_; k++) {
        int j = __shfl_sync(0xffffffffu, jv, k);
        float2 yv = *(const float2*)(g_yz + ((bbase + (size_t)j) << 7) + lane * 2);
        m0 = fmaxf(m0, yv.x);
        m1 = fmaxf(m1, yv.y);
    }

    float2 zv = *(const float2*)(g_yz + (p << 7) + 64 + lane * 2);
    float h0 = m0 + zv.x, h1 = m1 + zv.y;

    float s  = h0 + h1;
    float ss = h0 * h0 + h1 * h1;
#pragma unroll
    for (int off = 16; off; off >>= 1) {
        s  += __shfl_xor_sync(0xffffffffu, s, off);
        ss += __shfl_xor_sync(0xffffffffu, ss, off);
    }
    float mu  = s * (1.0f / 64.0f);
    float var = fmaxf(ss * (1.0f / 64.0f) - mu * mu, 0.0f);
    float rs  = rsqrtf(var + 1e-5f);

    float2 g  = *(const float2*)(gamma + lane * 2);
    float2 be = *(const float2*)(beta  + lane * 2);
    float hn0 = (h0 - mu) * rs * g.x + be.x;
    float hn1 = (h1 - mu) * rs * g.y + be.y;

    float r0 = 0.5f * hn0 * (1.0f + erff(hn0 * 0.7071067811865475f));
    float r1 = 0.5f * hn1 * (1.0f + erff(hn1 * 0.7071067811865475f));

    *(float2*)(out + (p << 6) + lane * 2) = make_float2(r0, r1);
}

// ---------------------------------------------------------------------------
extern "C" void kernel_launch(void* const* d_in, const int* in_sizes, int n_in,
                              void* d_out, int out_size)
{
    const float* x     = (const float*)d_in[0];
    const int*   ind   = (const int*)  d_in[1];
    const float* W     = (const float*)d_in[2];
    const float* gamma = (const float*)d_in[3];
    const float* beta  = (const float*)d_in[4];
    float*       out   = (float*)d_out;

    k1_gemm  <<<P_ / 128, 256>>>(x, W);
    k2_gather<<<P_ / 8,   256>>>(ind, gamma, beta, out);
}

// round 2
// speedup vs baseline: 2.2374x; 2.2374x over previous
#include <cuda_runtime.h>
#include <cstdint>

// EdgeConv: B=16, N=8192, K=20, D=64
// y[p][o] = x[p]·W1[o],  z[p][o] = x[p]·(W2[o]-W1[o])
// out = gelu(LN(z[p] + max_k y[ind[p][k]]))

#define B_  16
#define N_  8192
#define K_  20
#define P_  (B_ * N_)   // 131072 points

__device__ float g_y[(size_t)P_ * 64];   // 33.5 MB
__device__ float g_z[(size_t)P_ * 64];   // 33.5 MB

#define FMA2(d, a, b, c) \
    asm("fma.rn.f32x2 %0, %1, %2, %3;" : "=l"(d) : "l"(a), "l"(b), "l"(c))

__device__ __forceinline__ unsigned lo32(unsigned long long v) { return (unsigned)v; }
__device__ __forceinline__ unsigned hi32(unsigned long long v) { return (unsigned)(v >> 32); }

// ---------------------------------------------------------------------------
// Kernel 1: block tile = 128 points x 128 outputs, 256 threads.
// Thread tile = 4 points x 16 outputs.  og = tid&7 (o-group), pg = tid>>3.
// W in smem, chunk-permuted: logical o = og*16 + j*4 + e stored at
// phys float index d*128 + j*32 + og*4 + e  -> warp reads 128B contiguous.
// ---------------------------------------------------------------------------
__global__ __launch_bounds__(256, 2)
void k1_gemm(const float* __restrict__ x, const float* __restrict__ W)
{
    __shared__ float Wsm[64 * 128];   // 32 KB

    for (int i = threadIdx.x; i < 64 * 128; i += 256) {
        int d = i >> 7, o = i & 127;
        float v;
        if (o < 64) v = W[o * 128 + d];
        else        v = W[(o - 64) * 128 + 64 + d] - W[(o - 64) * 128 + d];
        int phys = d * 128 + ((o >> 2) & 3) * 32 + (o >> 4) * 4 + (o & 3);
        Wsm[phys] = v;
    }
    __syncthreads();

    const int og = threadIdx.x & 7;     // output group: logical o in [og*16, og*16+16)
    const int pg = threadIdx.x >> 3;    // point group : 4 points
    const size_t p0 = (size_t)blockIdx.x * 128 + (size_t)pg * 4;

    // acc[pt*8 + j*2 + h] : f32x2 pair (o = og*16 + j*4 + 2h .. +1)
    unsigned long long acc[32];
#pragma unroll
    for (int q = 0; q < 32; q++) acc[q] = 0ull;

    const float4* xb = (const float4*)(x + p0 * 64);   // 16 float4 per point

#pragma unroll 2
    for (int d4 = 0; d4 < 16; d4++) {
        float4 xc0 = __ldg(xb + d4);
        float4 xc1 = __ldg(xb + 16 + d4);
        float4 xc2 = __ldg(xb + 32 + d4);
        float4 xc3 = __ldg(xb + 48 + d4);
#pragma unroll
        for (int dd = 0; dd < 4; dd++) {
            const int d = d4 * 4 + dd;
            const float* wr = Wsm + d * 128 + og * 4;
            uint4 w0 = *(const uint4*)(wr);
            uint4 w1 = *(const uint4*)(wr + 32);
            uint4 w2 = *(const uint4*)(wr + 64);
            uint4 w3 = *(const uint4*)(wr + 96);
            unsigned long long wj[8];
            wj[0] = (unsigned long long)w0.x | ((unsigned long long)w0.y << 32);
            wj[1] = (unsigned long long)w0.z | ((unsigned long long)w0.w << 32);
            wj[2] = (unsigned long long)w1.x | ((unsigned long long)w1.y << 32);
            wj[3] = (unsigned long long)w1.z | ((unsigned long long)w1.w << 32);
            wj[4] = (unsigned long long)w2.x | ((unsigned long long)w2.y << 32);
            wj[5] = (unsigned long long)w2.z | ((unsigned long long)w2.w << 32);
            wj[6] = (unsigned long long)w3.x | ((unsigned long long)w3.y << 32);
            wj[7] = (unsigned long long)w3.z | ((unsigned long long)w3.w << 32);

            float xs[4] = { (&xc0.x)[dd], (&xc1.x)[dd], (&xc2.x)[dd], (&xc3.x)[dd] };
#pragma unroll
            for (int pt = 0; pt < 4; pt++) {
                unsigned long long pa;
                asm("mov.b64 %0, {%1, %1};" : "=l"(pa) : "r"(__float_as_uint(xs[pt])));
#pragma unroll
                for (int q = 0; q < 8; q++)
                    FMA2(acc[pt * 8 + q], pa, wj[q], acc[pt * 8 + q]);
            }
        }
    }

    // Store: og 0..3 -> y (o = og*16), og 4..7 -> z (o = (og-4)*16)
    float* base = (og < 4) ? (g_y + p0 * 64 + og * 16)
                           : (g_z + p0 * 64 + (og - 4) * 16);
#pragma unroll
    for (int pt = 0; pt < 4; pt++) {
        float4* dst = (float4*)(base + pt * 64);
#pragma unroll
        for (int j = 0; j < 4; j++) {
            unsigned long long a0 = acc[pt * 8 + j * 2];
            unsigned long long a1 = acc[pt * 8 + j * 2 + 1];
            float4 v;
            v.x = __uint_as_float(lo32(a0));
            v.y = __uint_as_float(hi32(a0));
            v.z = __uint_as_float(lo32(a1));
            v.w = __uint_as_float(hi32(a1));
            dst[j] = v;
        }
    }
}

// ---------------------------------------------------------------------------
// Kernel 2: warp per point, lane owns dims (2*lane, 2*lane+1).
// Shuffle precomputed 32-bit byte offsets (row = 256 B).
// ---------------------------------------------------------------------------
__global__ __launch_bounds__(256)
void k2_gather(const int*   __restrict__ ind,
               const float* __restrict__ gamma,
               const float* __restrict__ beta,
               float*       __restrict__ out)
{
    int warp = threadIdx.x >> 5, lane = threadIdx.x & 31;
    size_t p = (size_t)blockIdx.x * 8 + warp;
    size_t bbase = (p >> 13) << 13;   // b * N

    int off = 0;
    if (lane < K_) off = ind[p * K_ + lane] << 8;   // byte offset within batch block

    const char* ybase = (const char*)(g_y + (bbase << 6)) + lane * 8;

    float m0 = -3.402823466e+38f, m1 = -3.402823466e+38f;
#pragma unroll
    for (int k = 0; k < K_; k++) {
        int o = __shfl_sync(0xffffffffu, off, k);
        float2 yv = *(const float2*)(ybase + o);
        m0 = fmaxf(m0, yv.x);
        m1 = fmaxf(m1, yv.y);
    }

    float2 zv = *(const float2*)(g_z + (p << 6) + lane * 2);
    float h0 = m0 + zv.x, h1 = m1 + zv.y;

    float s  = h0 + h1;
    float ss = h0 * h0 + h1 * h1;
#pragma unroll
    for (int o2 = 16; o2; o2 >>= 1) {
        s  += __shfl_xor_sync(0xffffffffu, s, o2);
        ss += __shfl_xor_sync(0xffffffffu, ss, o2);
    }
    float mu  = s * (1.0f / 64.0f);
    float var = fmaxf(ss * (1.0f / 64.0f) - mu * mu, 0.0f);
    float rs  = rsqrtf(var + 1e-5f);

    float2 g  = *(const float2*)(gamma + lane * 2);
    float2 be = *(const float2*)(beta  + lane * 2);
    float hn0 = (h0 - mu) * rs * g.x + be.x;
    float hn1 = (h1 - mu) * rs * g.y + be.y;

    float r0 = 0.5f * hn0 * (1.0f + erff(hn0 * 0.7071067811865475f));
    float r1 = 0.5f * hn1 * (1.0f + erff(hn1 * 0.7071067811865475f));

    *(float2*)(out + (p << 6) + lane * 2) = make_float2(r0, r1);
}

// ---------------------------------------------------------------------------
extern "C" void kernel_launch(void* const* d_in, const int* in_sizes, int n_in,
                              void* d_out, int out_size)
{
    const float* x     = (const float*)d_in[0];
    const int*   ind   = (const int*)  d_in[1];
    const float* W     = (const float*)d_in[2];
    const float* gamma = (const float*)d_in[3];
    const float* beta  = (const float*)d_in[4];
    float*       out   = (float*)d_out;

    k1_gemm  <<<P_ / 128, 256>>>(x, W);
    k2_gather<<<P_ / 8,   256>>>(ind, gamma, beta, out);
}